// round 11
// baseline (speedup 1.0000x reference)
#include <cuda_runtime.h>
#include <math.h>

// Problem constants (fixed by setup_inputs)
#define BSZ   16
#define QN    900
#define CN    80
#define TN    1600
#define GS    3
#define NQ    (BSZ * QN)        // 14400
#define NROWS (NQ / GS)         // 4800 output rows
#define RPB   (QN / GS)         // 300 rows per batch

// Scratch (allocation-free rule: __device__ globals)
__device__ float  g_cc[NQ * CN];   // 2x focal class cost table [N, C] (labels = fast axis)
__device__ float4 g_qA[NQ];        // (5cx, 5cy, 5w, 5h)
__device__ float4 g_qB[NQ];        // (5x0, 5y0, 5x1, 5y1)
__device__ float  g_qC[NQ];        // 25*area
__device__ float4 g_tA[TN];        // (5cx, 5cy, 5w, 5h)
__device__ float4 g_tB[TN];        // (5x0, 5y0, 5x1, 5y1)
__device__ float2 g_tC[TN];        // (25*area, label-as-float-bits)

__device__ __forceinline__ float focal_cc2(float x) {
    float p   = 1.f / (1.f + __expf(-x));
    float om  = 1.f - p;
    float pos = 0.5f * om * om * (-__logf(p + 1e-8f));   // 2 * 0.25
    float neg = 1.5f * p  * p  * (-__logf(om + 1e-8f));  // 2 * 0.75
    return pos - neg;
}

// ---------------- fused prep ----------------
#define CCB 1125   // (NQ*CN/4)/256 blocks for the cc table
#define BXB 57     // ceil(NQ/256) blocks for boxes

__global__ __launch_bounds__(256) void prep_kernel(const float4* __restrict__ logits4,
                                                   const float*  __restrict__ qb,
                                                   const float*  __restrict__ tb,
                                                   const int*    __restrict__ tl) {
    int b = blockIdx.x;
    if (b < CCB) {
        int i = b * 256 + threadIdx.x;
        float4 x = logits4[i];
        float4 r;
        r.x = focal_cc2(x.x); r.y = focal_cc2(x.y);
        r.z = focal_cc2(x.z); r.w = focal_cc2(x.w);
        reinterpret_cast<float4*>(g_cc)[i] = r;
    } else {
        int i = (b - CCB) * 256 + threadIdx.x;
        if (i < NQ) {
            float cx = qb[i*4+0], cy = qb[i*4+1], w = qb[i*4+2], h = qb[i*4+3];
            float x0 = cx - 0.5f*w, y0 = cy - 0.5f*h;
            float x1 = cx + 0.5f*w, y1 = cy + 0.5f*h;
            float area = (x1 - x0) * (y1 - y0);          // reference rounding path, then scale
            g_qA[i] = make_float4(5.f*cx, 5.f*cy, 5.f*w, 5.f*h);
            g_qB[i] = make_float4(5.f*x0, 5.f*y0, 5.f*x1, 5.f*y1);
            g_qC[i] = 25.f * area;
        }
        if (i < TN) {
            float cx = tb[i*4+0], cy = tb[i*4+1], w = tb[i*4+2], h = tb[i*4+3];
            float x0 = cx - 0.5f*w, y0 = cy - 0.5f*h;
            float x1 = cx + 0.5f*w, y1 = cy + 0.5f*h;
            float area = (x1 - x0) * (y1 - y0);
            g_tA[i] = make_float4(5.f*cx, 5.f*cy, 5.f*w, 5.f*h);
            g_tB[i] = make_float4(5.f*x0, 5.f*y0, 5.f*x1, 5.f*y1);
            g_tC[i] = make_float2(25.f * area, __int_as_float(tl[i]));
        }
    }
}

// ---------------- main: R3 skeleton (rolled, low-reg) + adjacent-column STG.64 ----------------
#define THR  160     // 5 warps; block covers 320 adjacent columns
#define RCH  10      // output rows per block (300 % 10 == 0); grid = 5 x 480 = 2400 blocks
#define NQC  (RCH * GS)   // 30 queries per chunk

__device__ __forceinline__ float rcp_approx(float x) {
    float r; asm("rcp.approx.f32 %0, %1;" : "=f"(r) : "f"(x)); return r;
}

// All coords 5x-scaled, areas 25x; GIoU ratios are scale-invariant.
__device__ __forceinline__ float pair_cost(const float4 qA, const float4 qB, const float qC,
                                           const float4 tA, const float4 tB, const float tC,
                                           const float cc2) {
    // L1 (x5 pre-scaled; weight folded)
    float l1 = fabsf(qA.x - tA.x) + fabsf(qA.y - tA.y)
             + fabsf(qA.z - tA.z) + fabsf(qA.w - tA.w);
    // intersection (5x coords -> 25x areas)
    float ltx = fmaxf(qB.x, tB.x), lty = fmaxf(qB.y, tB.y);
    float rbx = fminf(qB.z, tB.z), rby = fminf(qB.w, tB.w);
    float dx = rbx - ltx,          dy = rby - lty;
    float wx = fmaxf(dx, 0.f),     wy = fmaxf(dy, 0.f);
    float inter = wx * wy;
    float uni = (qC + tC) - inter;
    // enclosing box: ewx = 5qw + 5tw - dx  (max(a,b) = a+b-min(a,b))
    float ewx = (qA.z + tA.z) - dx;
    float ewy = (qA.w + tA.w) - dy;
    float earea = ewx * ewy;
    // cost = l1 + cc2 + 2*(1 - uni/earea - inter/uni)
    float ru = rcp_approx(uni);
    float re = rcp_approx(earea);
    float s  = __fmaf_rn(-uni,   re, 1.0f);
    s        = __fmaf_rn(-inter, ru, s);
    return __fmaf_rn(2.f, s, l1 + cc2);
}

__global__ __launch_bounds__(THR, 12) void cost_kernel(float* __restrict__ out) {
    __shared__ float4 shA[NQC];
    __shared__ float4 shB[NQC];
    __shared__ float  shC[NQC];

    const int t0 = (blockIdx.x * THR + threadIdx.x) * 2;   // adjacent target columns t0, t0+1
    const int r0 = blockIdx.y * RCH;                       // first output row of this chunk
    const int nstart = (r0 / RPB) * QN + (r0 % RPB) * GS;  // 300 % RCH == 0: no batch crossing

    {
        int tid = threadIdx.x;
        if (tid < NQC)            shA[tid]         = g_qA[nstart + tid];
        else if (tid < 2*NQC)     shB[tid - NQC]   = g_qB[nstart + tid - NQC];
        else if (tid < 3*NQC)     shC[tid - 2*NQC] = g_qC[nstart + tid - 2*NQC];
    }
    __syncthreads();

    // target data -> registers (held for the whole chunk)
    const float4 tA0 = g_tA[t0],   tA1 = g_tA[t0+1];
    const float4 tB0 = g_tB[t0],   tB1 = g_tB[t0+1];
    const float2 tC0 = g_tC[t0],   tC1 = g_tC[t0+1];
    const float* ccp0 = g_cc + nstart * CN + __float_as_int(tC0.y);
    const float* ccp1 = g_cc + nstart * CN + __float_as_int(tC1.y);

    float* op = out + (size_t)r0 * TN + t0;
    const float4* qa = shA;
    const float4* qb = shB;
    const float*  qc = shC;

    #pragma unroll 2
    for (int rr = 0; rr < RCH; rr++) {
        float m0, m1;
        #pragma unroll
        for (int g = 0; g < GS; g++) {
            const float4 qA = qa[g];
            const float4 qB = qb[g];
            const float  qC = qc[g];
            const float cc0 = __ldg(ccp0 + g * CN);
            const float cc1 = __ldg(ccp1 + g * CN);
            float c0 = pair_cost(qA, qB, qC, tA0, tB0, tC0.x, cc0);
            float c1 = pair_cost(qA, qB, qC, tA1, tB1, tC1.x, cc1);
            if (g == 0) { m0 = c0; m1 = c1; }
            else        { m0 = fmaxf(m0, c0); m1 = fmaxf(m1, c1); }
        }
        *reinterpret_cast<float2*>(op) = make_float2(m0, m1);
        op   += TN;
        qa   += GS;  qb += GS;  qc += GS;
        ccp0 += GS * CN;
        ccp1 += GS * CN;
    }
}

extern "C" void kernel_launch(void* const* d_in, const int* in_sizes, int n_in,
                              void* d_out, int out_size) {
    const float* logits  = (const float*)d_in[0];  // [16,900,80]
    const float* pboxes  = (const float*)d_in[1];  // [16,900,4]
    const int*   tlabels = (const int*)  d_in[2];  // [1600]
    const float* tboxes  = (const float*)d_in[3];  // [1600,4]
    (void)in_sizes; (void)n_in; (void)out_size;

    prep_kernel<<<CCB + BXB, 256>>>((const float4*)logits, pboxes, tboxes, tlabels);
    cost_kernel<<<dim3(TN / (THR*2), NROWS / RCH), THR>>>((float*)d_out);
}

// round 12
// speedup vs baseline: 3.4150x; 3.4150x over previous
#include <cuda_runtime.h>
#include <math.h>

// Problem constants (fixed by setup_inputs)
#define BSZ   16
#define QN    900
#define CN    80
#define TN    1600
#define GS    3
#define NQ    (BSZ * QN)        // 14400
#define NROWS (NQ / GS)         // 4800 output rows
#define RPB   (QN / GS)         // 300 rows per batch

// Scratch (allocation-free rule: __device__ globals)
__device__ float  g_cc[NQ * CN];            // 2x focal class cost table [N, C]
__device__ float4 g_qd[NQ * 3];             // per-query:  [5cx,5cy,5w,5h][x0,y0,x1,y1][area,w,h,-]
__device__ float4 g_td[TN * 3];             // per-target: [5cx,5cy,5w,5h][x0,y0,x1,y1][area,w,h,label]

__device__ __forceinline__ float focal_cc2(float x) {
    float p   = 1.f / (1.f + __expf(-x));
    float om  = 1.f - p;
    float pos = 0.5f * om * om * (-__logf(p + 1e-8f));   // 2 * 0.25
    float neg = 1.5f * p  * p  * (-__logf(om + 1e-8f));  // 2 * 0.75
    return pos - neg;
}

// ---------------- fused prep ----------------
#define CCB 1125   // (NQ*CN/4)/256 blocks for the cc table
#define BXB 57     // ceil(NQ/256) blocks for boxes

__global__ __launch_bounds__(256) void prep_kernel(const float4* __restrict__ logits4,
                                                   const float*  __restrict__ qb,
                                                   const float*  __restrict__ tb,
                                                   const int*    __restrict__ tl) {
    int b = blockIdx.x;
    if (b < CCB) {
        int i = b * 256 + threadIdx.x;
        float4 x = logits4[i];
        float4 r;
        r.x = focal_cc2(x.x); r.y = focal_cc2(x.y);
        r.z = focal_cc2(x.z); r.w = focal_cc2(x.w);
        reinterpret_cast<float4*>(g_cc)[i] = r;
    } else {
        int i = (b - CCB) * 256 + threadIdx.x;
        if (i < NQ) {
            float cx = qb[i*4+0], cy = qb[i*4+1], w = qb[i*4+2], h = qb[i*4+3];
            float x0 = cx - 0.5f*w, y0 = cy - 0.5f*h;
            float x1 = cx + 0.5f*w, y1 = cy + 0.5f*h;
            float ww = x1 - x0, hh = y1 - y0;
            float area = ww * hh;                       // same rounding path as reference
            g_qd[i*3+0] = make_float4(5.f*cx, 5.f*cy, 5.f*w, 5.f*h);
            g_qd[i*3+1] = make_float4(x0, y0, x1, y1);
            g_qd[i*3+2] = make_float4(area, ww, hh, 0.f);
        }
        if (i < TN) {
            float cx = tb[i*4+0], cy = tb[i*4+1], w = tb[i*4+2], h = tb[i*4+3];
            float x0 = cx - 0.5f*w, y0 = cy - 0.5f*h;
            float x1 = cx + 0.5f*w, y1 = cy + 0.5f*h;
            float ww = x1 - x0, hh = y1 - y0;
            float area = ww * hh;
            g_td[i*3+0] = make_float4(5.f*cx, 5.f*cy, 5.f*w, 5.f*h);
            g_td[i*3+1] = make_float4(x0, y0, x1, y1);
            g_td[i*3+2] = make_float4(area, ww, hh, __int_as_float(tl[i]));
        }
    }
}

// ---------------- main: fused cost + group-max, 2 adjacent columns per thread ----------------
#define THR  160     // 5 warps; block covers 320 adjacent columns
#define RCH  10      // output rows per block (300 % 10 == 0; grid = 5 x 480 = 2400 blocks)

__device__ __forceinline__ float rcp_approx(float x) {
    float r; asm("rcp.approx.f32 %0, %1;" : "=f"(r) : "f"(x)); return r;
}

__device__ __forceinline__ float pair_cost(const float4 qA, const float4 qB, const float4 qC,
                                           const float4 tA, const float4 tB, const float4 tC,
                                           const float cc2) {
    // L1 box cost (inputs pre-scaled by 5)
    float l1 = fabsf(qA.x - tA.x) + fabsf(qA.y - tA.y)
             + fabsf(qA.z - tA.z) + fabsf(qA.w - tA.w);
    // intersection
    float ltx = fmaxf(qB.x, tB.x), lty = fmaxf(qB.y, tB.y);
    float rbx = fminf(qB.z, tB.z), rby = fminf(qB.w, tB.w);
    float dx = rbx - ltx,          dy = rby - lty;
    float wx = fmaxf(dx, 0.f),     wy = fmaxf(dy, 0.f);
    float inter = wx * wy;
    float uni = (qC.x + tC.x) - inter;
    // enclosing box via max(a,b) = a+b-min(a,b):  ewx = qw + tw - dx
    float ewx = (qC.y + tC.y) - dx;
    float ewy = (qC.z + tC.z) - dy;
    float earea = ewx * ewy;
    // cost = l1(x5) + cc(x2) + 2*(1 - uni/earea - inter/uni)
    float ru = rcp_approx(uni);
    float re = rcp_approx(earea);
    float s  = __fmaf_rn(-uni,   re, 1.0f);
    s        = __fmaf_rn(-inter, ru, s);
    return __fmaf_rn(2.f, s, l1 + cc2);
}

__global__ __launch_bounds__(THR) void cost_kernel(float* __restrict__ out) {
    __shared__ float4 shq[RCH * 3 * 3];              // 30 queries x 3 float4 = 1.44 KB

    const int t0 = (blockIdx.x * THR + threadIdx.x) * 2;   // adjacent target columns t0, t0+1
    const int r0 = blockIdx.y * RCH;                       // first output row of this chunk
    const int nstart = (r0 / RPB) * QN + (r0 % RPB) * GS;

    if (threadIdx.x < RCH * 9) shq[threadIdx.x] = g_qd[nstart * 3 + threadIdx.x];
    __syncthreads();

    // target data -> registers (held for the whole chunk)
    const float4 tA0 = g_td[t0*3+0], tB0 = g_td[t0*3+1], tC0 = g_td[t0*3+2];
    const float4 tA1 = g_td[t0*3+3], tB1 = g_td[t0*3+4], tC1 = g_td[t0*3+5];
    const float* ccp0 = g_cc + nstart * CN + __float_as_int(tC0.w);
    const float* ccp1 = g_cc + nstart * CN + __float_as_int(tC1.w);

    float* op = out + (size_t)r0 * TN + t0;
    int nb = 0;

    #pragma unroll 2
    for (int rr = 0; rr < RCH; rr++, nb += GS) {
        float m0, m1;
        #pragma unroll
        for (int g = 0; g < GS; g++) {
            const float4 qA = shq[(rr*3 + g)*3 + 0];
            const float4 qB = shq[(rr*3 + g)*3 + 1];
            const float4 qC = shq[(rr*3 + g)*3 + 2];
            const float cc0 = __ldg(ccp0 + (nb + g) * CN);
            const float cc1 = __ldg(ccp1 + (nb + g) * CN);
            float c0 = pair_cost(qA, qB, qC, tA0, tB0, tC0, cc0);
            float c1 = pair_cost(qA, qB, qC, tA1, tB1, tC1, cc1);
            if (g == 0) { m0 = c0; m1 = c1; }
            else        { m0 = fmaxf(m0, c0); m1 = fmaxf(m1, c1); }
        }
        *reinterpret_cast<float2*>(op) = make_float2(m0, m1);
        op += TN;
    }
}

extern "C" void kernel_launch(void* const* d_in, const int* in_sizes, int n_in,
                              void* d_out, int out_size) {
    const float* logits  = (const float*)d_in[0];  // [16,900,80]
    const float* pboxes  = (const float*)d_in[1];  // [16,900,4]
    const int*   tlabels = (const int*)  d_in[2];  // [1600]
    const float* tboxes  = (const float*)d_in[3];  // [1600,4]
    (void)in_sizes; (void)n_in; (void)out_size;

    prep_kernel<<<CCB + BXB, 256>>>((const float4*)logits, pboxes, tboxes, tlabels);
    cost_kernel<<<dim3(800 / THR, NROWS / RCH), THR>>>((float*)d_out);
}